// round 1
// baseline (speedup 1.0000x reference)
#include <cuda_runtime.h>

// FCOS head decode: 32 x 128 x 128 pixels, 80 classes.
// Inputs (metadata order):
//   d_in[0] t_ltrb        [32,128,128,4]  f32
//   d_in[1] center_logits [32,128,128,1]  f32
//   d_in[2] cls_logits    [32,128,128,80] f32
//   d_in[3] img_h (unused), d_in[4] img_w (unused)
// Output (f32, concatenated in reference return order):
//   [0          , 2097152) : p_xywh  flat
//   [2097152    , 2621440) : cls_idx as float
//   [2621440    , 3145728) : confs

#define NB   32
#define NH   128
#define NW   128
#define NCLS 80
#define HW   (NH * NW)
#define NPIX (NB * HW)          // 524288
#define STRIDE_F 8.0f

__global__ __launch_bounds__(256, 8)
void fcos_decode_kernel(const float* __restrict__ t_ltrb,
                        const float* __restrict__ center,
                        const float* __restrict__ cls,
                        float* __restrict__ out)
{
    const int gwarp = (blockIdx.x * blockDim.x + threadIdx.x) >> 5;  // pixel id
    const int lane  = threadIdx.x & 31;
    if (gwarp >= NPIX) return;

    // ---- coalesced class-logit read: lanes cover [lane, lane+32, lane+64] ----
    const float* __restrict__ c = cls + (long long)gwarp * NCLS;
    float m  = c[lane];
    int   mi = lane;
    float v1 = c[lane + 32];
    if (v1 > m) { m = v1; mi = lane + 32; }
    if (lane < NCLS - 64) {                 // lanes 0..15 own idx 64..79
        float v2 = c[lane + 64];
        if (v2 > m) { m = v2; mi = lane + 64; }
    }

    // ---- warp max+argmax, first-index tie-break (matches jnp.argmax) ----
    #pragma unroll
    for (int off = 16; off > 0; off >>= 1) {
        float ov = __shfl_xor_sync(0xffffffffu, m,  off);
        int   oi = __shfl_xor_sync(0xffffffffu, mi, off);
        if (ov > m || (ov == m && oi < mi)) { m = ov; mi = oi; }
    }

    if (lane == 0) {
        // ltrb decode: p = exp(t) * stride
        float4 t = *reinterpret_cast<const float4*>(t_ltrb + (long long)gwarp * 4);
        float pl = __expf(t.x) * STRIDE_F;
        float pt = __expf(t.y) * STRIDE_F;
        float pr = __expf(t.z) * STRIDE_F;
        float pb = __expf(t.w) * STRIDE_F;

        int hw = gwarp & (HW - 1);
        int hy = hw >> 7;          // row  (NW = 128)
        int wx = hw & (NW - 1);    // col
        float cx0 = (float)wx * STRIDE_F + STRIDE_F * 0.5f;
        float cy0 = (float)hy * STRIDE_F + STRIDE_F * 0.5f;

        float4 o;
        o.x = cx0 + (pr - pl) * 0.5f;   // cx
        o.y = cy0 + (pb - pt) * 0.5f;   // cy
        o.z = pl + pr;                  // w
        o.w = pt + pb;                  // h
        *reinterpret_cast<float4*>(out + (long long)gwarp * 4) = o;

        // conf = sqrt(sigmoid(center) * sigmoid(max_logit))  (sigmoid monotone)
        float pc = 1.0f / (1.0f + __expf(-center[gwarp]));
        float ps = 1.0f / (1.0f + __expf(-m));

        out[(long long)NPIX * 4 + gwarp] = (float)mi;
        out[(long long)NPIX * 5 + gwarp] = sqrtf(pc * ps);
    }
}

extern "C" void kernel_launch(void* const* d_in, const int* in_sizes, int n_in,
                              void* d_out, int out_size)
{
    const float* t_ltrb = (const float*)d_in[0];
    const float* center = (const float*)d_in[1];
    const float* cls    = (const float*)d_in[2];
    float* out = (float*)d_out;

    // one warp per pixel, 8 warps per block
    const int threads = 256;
    const int warps_per_block = threads / 32;
    const int blocks = (NPIX + warps_per_block - 1) / warps_per_block;  // 65536
    fcos_decode_kernel<<<blocks, threads>>>(t_ltrb, center, cls, out);
}

// round 3
// speedup vs baseline: 2.4938x; 2.4938x over previous
#include <cuda_runtime.h>

// FCOS head decode: 32 x 128 x 128 pixels, 80 classes.
// Inputs (metadata order):
//   d_in[0] t_ltrb        [32,128,128,4]  f32
//   d_in[1] center_logits [32,128,128,1]  f32
//   d_in[2] cls_logits    [32,128,128,80] f32
//   d_in[3] img_h (unused), d_in[4] img_w (unused)
// Output (f32, concatenated in reference return order):
//   [0       , 2097152) : p_xywh flat
//   [2097152 , 2621440) : cls_idx as float
//   [2621440 , 3145728) : confs

#define NB   32
#define NH   128
#define NW   128
#define NCLS 80
#define HW   (NH * NW)
#define NPIX (NB * HW)          // 524288
#define STRIDE_F 8.0f

#define TPB   128               // threads per block == pixels per block
#define F4PP  (NCLS / 4)        // 20 float4 per pixel
#define ROWF  84                // padded smem row stride (floats); 336B, 16B aligned

__global__ __launch_bounds__(TPB, 5)
void fcos_decode_kernel(const float* __restrict__ t_ltrb,
                        const float* __restrict__ center,
                        const float* __restrict__ cls,
                        float* __restrict__ out)
{
    __shared__ float s[TPB * ROWF];          // 43008 B

    const int tid = threadIdx.x;
    const long long pixBase = (long long)blockIdx.x * TPB;

    // ---- stage 128 pixels' cls logits: coalesced float4 global loads ----
    const float4* __restrict__ cls4 =
        reinterpret_cast<const float4*>(cls + pixBase * NCLS);
    #pragma unroll
    for (int i = 0; i < F4PP; i++) {
        int j = tid + i * TPB;               // 0 .. 2559
        float4 v = cls4[j];
        int pix = j / F4PP;                  // 80 % 4 == 0: float4 never crosses a pixel
        int c4  = j - pix * F4PP;
        *reinterpret_cast<float4*>(&s[pix * ROWF + c4 * 4]) = v;
    }
    __syncthreads();

    // ---- each thread: max+argmax over its own 80 values (first-index ties) ----
    float m = -__int_as_float(0x7f800000);   // -inf
    int   mi = 0;
    const float4* __restrict__ row = reinterpret_cast<const float4*>(&s[tid * ROWF]);
    #pragma unroll
    for (int k = 0; k < F4PP; k++) {
        float4 v = row[k];
        int b = k * 4;
        if (v.x > m) { m = v.x; mi = b;     }
        if (v.y > m) { m = v.y; mi = b + 1; }
        if (v.z > m) { m = v.z; mi = b + 2; }
        if (v.w > m) { m = v.w; mi = b + 3; }
    }

    const long long gp = pixBase + tid;      // global pixel id

    // ---- ltrb decode: p = exp(t) * stride ----
    float4 t = *reinterpret_cast<const float4*>(t_ltrb + gp * 4);
    float pl = __expf(t.x) * STRIDE_F;
    float pt = __expf(t.y) * STRIDE_F;
    float pr = __expf(t.z) * STRIDE_F;
    float pb = __expf(t.w) * STRIDE_F;

    int hw = (int)(gp & (HW - 1));
    int hy = hw >> 7;                        // NW = 128
    int wx = hw & (NW - 1);
    float cx0 = (float)wx * STRIDE_F + STRIDE_F * 0.5f;
    float cy0 = (float)hy * STRIDE_F + STRIDE_F * 0.5f;

    float4 o;
    o.x = cx0 + (pr - pl) * 0.5f;            // cx
    o.y = cy0 + (pb - pt) * 0.5f;            // cy
    o.z = pl + pr;                           // w
    o.w = pt + pb;                           // h
    *reinterpret_cast<float4*>(out + gp * 4) = o;

    // conf = sqrt(sigmoid(center) * sigmoid(max_logit))  (sigmoid monotone)
    float pc = 1.0f / (1.0f + __expf(-center[gp]));
    float ps = 1.0f / (1.0f + __expf(-m));

    out[(long long)NPIX * 4 + gp] = (float)mi;
    out[(long long)NPIX * 5 + gp] = sqrtf(pc * ps);
}

extern "C" void kernel_launch(void* const* d_in, const int* in_sizes, int n_in,
                              void* d_out, int out_size)
{
    const float* t_ltrb = (const float*)d_in[0];
    const float* center = (const float*)d_in[1];
    const float* cls    = (const float*)d_in[2];
    float* out = (float*)d_out;

    fcos_decode_kernel<<<NPIX / TPB, TPB>>>(t_ltrb, center, cls, out);
}

// round 5
// speedup vs baseline: 3.2529x; 1.3044x over previous
#include <cuda_runtime.h>

// FCOS head decode: 32 x 128 x 128 pixels, 80 classes.
// Inputs (metadata order):
//   d_in[0] t_ltrb        [32,128,128,4]  f32
//   d_in[1] center_logits [32,128,128,1]  f32
//   d_in[2] cls_logits    [32,128,128,80] f32
//   d_in[3] img_h (unused), d_in[4] img_w (unused)
// Output (f32, concatenated in reference return order):
//   [0       , 2097152) : p_xywh flat
//   [2097152 , 2621440) : cls_idx as float
//   [2621440 , 3145728) : confs

#define NB   32
#define NH   128
#define NW   128
#define NCLS 80
#define HW   (NH * NW)
#define NPIX (NB * HW)          // 524288
#define STRIDE_F 8.0f

#define TPB   256               // threads per block; 4 threads (a quad) per pixel
#define F4PP  (NCLS / 4)        // 20 float4 per pixel
#define RPT   (F4PP / 4)        // 5 float4 per thread

__global__ __launch_bounds__(TPB)
void fcos_decode_kernel(const float* __restrict__ t_ltrb,
                        const float* __restrict__ center,
                        const float* __restrict__ cls,
                        float* __restrict__ out)
{
    const int gtid = blockIdx.x * TPB + threadIdx.x;
    const int pix  = gtid >> 2;              // pixel id
    const int q    = gtid & 3;               // quad lane

    // ---- direct global loads: thread q owns float4s {q, q+4, ..., q+16} ----
    // Warp request = 8 pixels x 64B windows -> 8 distinct 128B lines, all
    // consumed by this warp's 5 back-to-back loads (L1-resident, 2x wf amp).
    const float4* __restrict__ c4 =
        reinterpret_cast<const float4*>(cls) + (long long)pix * F4PP + q;
    float4 v[RPT];
    #pragma unroll
    for (int r = 0; r < RPT; r++) v[r] = c4[r * 4];

    // ---- per-thread max+argmax (class indices increasing -> '>' keeps first) ----
    float m  = -__int_as_float(0x7f800000);  // -inf
    int   mi = 0;
    #pragma unroll
    for (int r = 0; r < RPT; r++) {
        int b = (q + r * 4) * 4;             // global class index of v[r].x
        if (v[r].x > m) { m = v[r].x; mi = b;     }
        if (v[r].y > m) { m = v[r].y; mi = b + 1; }
        if (v[r].z > m) { m = v[r].z; mi = b + 2; }
        if (v[r].w > m) { m = v[r].w; mi = b + 3; }
    }

    // ---- intra-quad reduce, first-index tie-break (matches jnp.argmax) ----
    #pragma unroll
    for (int off = 1; off <= 2; off <<= 1) {
        float ov = __shfl_xor_sync(0xffffffffu, m,  off);
        int   oi = __shfl_xor_sync(0xffffffffu, mi, off);
        if (ov > m || (ov == m && oi < mi)) { m = ov; mi = oi; }
    }

    if (q == 0) {
        const long long gp = pix;

        // ltrb decode: p = exp(t) * stride
        float4 t = *reinterpret_cast<const float4*>(t_ltrb + gp * 4);
        float pl = __expf(t.x) * STRIDE_F;
        float pt = __expf(t.y) * STRIDE_F;
        float pr = __expf(t.z) * STRIDE_F;
        float pb = __expf(t.w) * STRIDE_F;

        int hw = pix & (HW - 1);
        int hy = hw >> 7;                    // NW = 128
        int wx = hw & (NW - 1);
        float cx0 = (float)wx * STRIDE_F + STRIDE_F * 0.5f;
        float cy0 = (float)hy * STRIDE_F + STRIDE_F * 0.5f;

        float4 o;
        o.x = cx0 + (pr - pl) * 0.5f;        // cx
        o.y = cy0 + (pb - pt) * 0.5f;        // cy
        o.z = pl + pr;                       // w
        o.w = pt + pb;                       // h
        *reinterpret_cast<float4*>(out + gp * 4) = o;

        // conf = sqrt(sigmoid(center) * sigmoid(max_logit))  (sigmoid monotone)
        float pc = 1.0f / (1.0f + __expf(-center[gp]));
        float ps = 1.0f / (1.0f + __expf(-m));

        out[(long long)NPIX * 4 + gp] = (float)mi;
        out[(long long)NPIX * 5 + gp] = sqrtf(pc * ps);
    }
}

extern "C" void kernel_launch(void* const* d_in, const int* in_sizes, int n_in,
                              void* d_out, int out_size)
{
    const float* t_ltrb = (const float*)d_in[0];
    const float* center = (const float*)d_in[1];
    const float* cls    = (const float*)d_in[2];
    float* out = (float*)d_out;

    const int total_threads = NPIX * 4;      // 4 threads per pixel
    fcos_decode_kernel<<<total_threads / TPB, TPB>>>(t_ltrb, center, cls, out);
}